// round 1
// baseline (speedup 1.0000x reference)
#include <cuda_runtime.h>
#include <math.h>

// ============================================================================
// Scratch (single __device__ array, no allocations anywhere)
// ============================================================================
// Layout (floats):
//   LN     @ 0          4096*1024  =  4,194,304
//   QKV    @ 4194304    4096*3072  = 12,582,912
//   ATTN   @ 16777216   4096*1024
//   X1     @ 20971520   4096*1024
//   X2     @ 25165824   4096*1024
//   QDEC   @ 29360128   4096*1024
//   ENCKV  @ 33554432   1028*2048  =  2,105,344
//   H1     @ 35659776   4096*4096  = 16,777,216
//   H      @ 52436992   4096*1024
//   A1     @ 56631296   4096*256   =  1,048,576
//   total = 57,679,872 floats (~230 MB)
__device__ float g_scratch[57679872];

#define OFF_LN     0ul
#define OFF_QKV    4194304ul
#define OFF_ATTN   16777216ul
#define OFF_X1     20971520ul
#define OFF_X2     25165824ul
#define OFF_QDEC   29360128ul
#define OFF_ENCKV  33554432ul
#define OFF_H1     35659776ul
#define OFF_H      52436992ul
#define OFF_A1     56631296ul

// ============================================================================
// LayerNorm: one block per row, C=1024, 256 threads
// ============================================================================
__global__ void ln_kernel(const float* __restrict__ x, const float* __restrict__ g,
                          const float* __restrict__ b, float* __restrict__ out) {
    const int C = 1024;
    int row = blockIdx.x;
    const float* xr = x + (size_t)row * C;
    float s = 0.f, ss = 0.f;
    for (int i = threadIdx.x; i < C; i += 256) { float v = xr[i]; s += v; ss += v * v; }
    #pragma unroll
    for (int o = 16; o; o >>= 1) {
        s  += __shfl_xor_sync(0xffffffffu, s, o);
        ss += __shfl_xor_sync(0xffffffffu, ss, o);
    }
    __shared__ float rs[8], rss[8];
    __shared__ float sh_m, sh_r;
    int w = threadIdx.x >> 5;
    if ((threadIdx.x & 31) == 0) { rs[w] = s; rss[w] = ss; }
    __syncthreads();
    if (threadIdx.x == 0) {
        float S = 0.f, SS = 0.f;
        #pragma unroll
        for (int i = 0; i < 8; i++) { S += rs[i]; SS += rss[i]; }
        float m = S / C;
        float v = SS / C - m * m;
        sh_m = m; sh_r = rsqrtf(v + 1e-5f);
    }
    __syncthreads();
    float m = sh_m, rst = sh_r;
    float* orow = out + (size_t)row * C;
    for (int i = threadIdx.x; i < C; i += 256)
        orow[i] = (xr[i] - m) * rst * g[i] + b[i];
}

// ============================================================================
// SGEMM: C[M,N] = A[M,K] @ B[K,N] + bias (+res1)(+res2), optional GELU.
// 64x64 tile, BK=16, 256 threads, 4x4 microtile per thread.
// A row-major lda, B row-major ldb (supports column-sliced weights via ptr+off).
// res1/res2 have the same [M,ldc] layout as C.
// ============================================================================
__device__ __forceinline__ float gelu_tanh(float v) {
    float u = 0.7978845608028654f * (v + 0.044715f * v * v * v);
    return 0.5f * v * (1.f + tanhf(u));
}

__global__ void sgemm_kernel(const float* __restrict__ A, int lda,
                             const float* __restrict__ B, int ldb,
                             const float* __restrict__ bias,
                             const float* __restrict__ res1,
                             const float* __restrict__ res2,
                             float* __restrict__ C, int ldc,
                             int M, int N, int K, int dogelu) {
    __shared__ float As[16][64];   // transposed: As[k][m]
    __shared__ float Bs[16][64];
    int bm = blockIdx.y * 64, bn = blockIdx.x * 64;
    int tid = threadIdx.x;
    int tx = tid & 15, ty = tid >> 4;

    float acc[4][4] = {};

    int arow  = tid >> 2;          // 0..63
    int acol4 = (tid & 3) * 4;     // 0,4,8,12
    int brow  = tid >> 4;          // 0..15
    int bcol4 = (tid & 15) * 4;    // 0..60

    const float* Aptr = A + (size_t)(bm + arow) * lda + acol4;
    const float* Bptr = B + (size_t)brow * ldb + bn + bcol4;
    bool aval = (bm + arow) < M;

    for (int k0 = 0; k0 < K; k0 += 16) {
        float4 a4 = aval ? *(const float4*)(Aptr + k0) : make_float4(0.f, 0.f, 0.f, 0.f);
        float4 b4 = *(const float4*)(Bptr + (size_t)k0 * ldb);
        As[acol4 + 0][arow] = a4.x;
        As[acol4 + 1][arow] = a4.y;
        As[acol4 + 2][arow] = a4.z;
        As[acol4 + 3][arow] = a4.w;
        *(float4*)&Bs[brow][bcol4] = b4;
        __syncthreads();
        #pragma unroll
        for (int kk = 0; kk < 16; kk++) {
            float4 av = *(const float4*)&As[kk][ty * 4];
            float4 bv = *(const float4*)&Bs[kk][tx * 4];
            float a[4] = {av.x, av.y, av.z, av.w};
            float b[4] = {bv.x, bv.y, bv.z, bv.w};
            #pragma unroll
            for (int i = 0; i < 4; i++)
                #pragma unroll
                for (int j = 0; j < 4; j++)
                    acc[i][j] += a[i] * b[j];
        }
        __syncthreads();
    }

    #pragma unroll
    for (int i = 0; i < 4; i++) {
        int r = bm + ty * 4 + i;
        if (r >= M) continue;
        #pragma unroll
        for (int j = 0; j < 4; j++) {
            int c = bn + tx * 4 + j;
            float v = acc[i][j] + bias[c];
            size_t idx = (size_t)r * ldc + c;
            if (res1) v += res1[idx];
            if (res2) v += res2[idx];
            if (dogelu) v = gelu_tanh(v);
            C[idx] = v;
        }
    }
}

// ============================================================================
// Flash-style attention, fp32, D=64 per head, 64-row Q tiles, online softmax.
// grid = (Tq/64, H, B), 256 threads. Each thread owns 1 S/O row x 16 cols.
// Q/K/V are base pointers with token stride (qts/kts) and batch stride.
// O written merged-heads [B, Tq, H*64].
// ============================================================================
#define AT_PAD 68

template <bool CAUSAL>
__global__ void attn_kernel(const float* __restrict__ Qb, long qts, long qbs,
                            const float* __restrict__ Kb, long kts, long kbs,
                            const float* __restrict__ Vb,
                            float* __restrict__ O,
                            int Tq, int Tk, float scale) {
    extern __shared__ float sm[];
    float* Qs = sm;                    // [64][AT_PAD]
    float* Ks = Qs + 64 * AT_PAD;
    float* Vs = Ks + 64 * AT_PAD;
    float* Ss = Vs + 64 * AT_PAD;

    int b = blockIdx.z, h = blockIdx.y, qt = blockIdx.x;
    int tid = threadIdx.x;
    const float* Qp = Qb + (size_t)b * qbs + (size_t)h * 64;
    const float* Kp = Kb + (size_t)b * kbs + (size_t)h * 64;
    const float* Vp = Vb + (size_t)b * kbs + (size_t)h * 64;

    // load Q tile: 64x64 floats, 4 float4 per thread
    #pragma unroll
    for (int it = 0; it < 4; it++) {
        int idx = tid + it * 256;
        int r = idx >> 4, c4 = (idx & 15) << 2;
        int t = qt * 64 + r;
        float4 v = *(const float4*)(Qp + (size_t)t * qts + c4);
        *(float4*)&Qs[r * AT_PAD + c4] = v;
    }

    int r  = tid >> 2;            // owned row 0..63
    int c0 = (tid & 3) * 16;      // owned col block
    int q_global = qt * 64 + r;

    float o[16];
    #pragma unroll
    for (int j = 0; j < 16; j++) o[j] = 0.f;
    float mreg = -1e30f, lreg = 0.f;

    int ktiles = CAUSAL ? (qt + 1) : (Tk + 63) / 64;

    for (int kt = 0; kt < ktiles; kt++) {
        __syncthreads();  // prior-iter Ss/Vs reads done; also makes Qs visible on iter 0
        #pragma unroll
        for (int it = 0; it < 4; it++) {
            int idx = tid + it * 256;
            int rr = idx >> 4, c4 = (idx & 15) << 2;
            int t = kt * 64 + rr;
            float4 kv, vv;
            if (t < Tk) {
                kv = *(const float4*)(Kp + (size_t)t * kts + c4);
                vv = *(const float4*)(Vp + (size_t)t * kts + c4);
            } else {
                kv = make_float4(0.f, 0.f, 0.f, 0.f);
                vv = kv;
            }
            *(float4*)&Ks[rr * AT_PAD + c4] = kv;
            *(float4*)&Vs[rr * AT_PAD + c4] = vv;
        }
        __syncthreads();

        // S[r][c0..c0+15]
        float sv[16];
        #pragma unroll
        for (int j = 0; j < 16; j++) sv[j] = 0.f;
        #pragma unroll 4
        for (int d = 0; d < 64; d += 4) {
            float4 qv = *(const float4*)&Qs[r * AT_PAD + d];
            #pragma unroll
            for (int cc = 0; cc < 16; cc++) {
                float4 kv = *(const float4*)&Ks[(c0 + cc) * AT_PAD + d];
                sv[cc] += qv.x * kv.x + qv.y * kv.y + qv.z * kv.z + qv.w * kv.w;
            }
        }
        float tmax = -1e30f;
        #pragma unroll
        for (int cc = 0; cc < 16; cc++) {
            int kg = kt * 64 + c0 + cc;
            bool valid = (kg < Tk) && (!CAUSAL || kg <= q_global);
            sv[cc] = valid ? sv[cc] * scale : -1e30f;
            tmax = fmaxf(tmax, sv[cc]);
        }
        tmax = fmaxf(tmax, __shfl_xor_sync(0xffffffffu, tmax, 1));
        tmax = fmaxf(tmax, __shfl_xor_sync(0xffffffffu, tmax, 2));
        float mnew  = fmaxf(mreg, tmax);
        float alpha = __expf(mreg - mnew);
        float psum = 0.f;
        #pragma unroll
        for (int cc = 0; cc < 16; cc++) {
            float p = __expf(sv[cc] - mnew);
            Ss[r * AT_PAD + c0 + cc] = p;
            psum += p;
        }
        psum += __shfl_xor_sync(0xffffffffu, psum, 1);
        psum += __shfl_xor_sync(0xffffffffu, psum, 2);
        lreg = lreg * alpha + psum;
        mreg = mnew;
        #pragma unroll
        for (int j = 0; j < 16; j++) o[j] *= alpha;
        __syncwarp();  // Ss row written by this 4-lane group; reads below are same-warp

        // O[r][c0..c0+15] += P[r][:] @ Vs[:, c0..c0+15]
        #pragma unroll 4
        for (int k = 0; k < 64; k++) {
            float p = Ss[r * AT_PAD + k];
            #pragma unroll
            for (int j4 = 0; j4 < 4; j4++) {
                float4 vv = *(const float4*)&Vs[k * AT_PAD + c0 + j4 * 4];
                o[j4 * 4 + 0] += p * vv.x;
                o[j4 * 4 + 1] += p * vv.y;
                o[j4 * 4 + 2] += p * vv.z;
                o[j4 * 4 + 3] += p * vv.w;
            }
        }
    }

    float inv = 1.f / lreg;
    float* Op = O + ((size_t)(b * Tq + q_global)) * 1024 + h * 64 + c0;
    #pragma unroll
    for (int j4 = 0; j4 < 4; j4++) {
        float4 v = make_float4(o[j4 * 4 + 0] * inv, o[j4 * 4 + 1] * inv,
                               o[j4 * 4 + 2] * inv, o[j4 * 4 + 3] * inv);
        *(float4*)(Op + j4 * 4) = v;
    }
}

// ============================================================================
// Launch
// ============================================================================
extern "C" void kernel_launch(void* const* d_in, const int* in_sizes, int n_in,
                              void* d_out, int out_size) {
    (void)in_sizes; (void)n_in; (void)out_size;
    const float* x        = (const float*)d_in[0];
    const float* enc      = (const float*)d_in[1];
    // d_in[2] = prefix_embd (unused)
    const float* ln1_g    = (const float*)d_in[3];
    const float* ln1_b    = (const float*)d_in[4];
    const float* ln2_g    = (const float*)d_in[5];
    const float* ln2_b    = (const float*)d_in[6];
    const float* ln3_g    = (const float*)d_in[7];
    const float* ln3_b    = (const float*)d_in[8];
    const float* attn_w   = (const float*)d_in[9];
    const float* attn_b   = (const float*)d_in[10];
    const float* aproj_w  = (const float*)d_in[11];
    const float* aproj_b  = (const float*)d_in[12];
    const float* ca_w     = (const float*)d_in[13];
    const float* ca_b     = (const float*)d_in[14];
    const float* caproj_w = (const float*)d_in[15];
    const float* caproj_b = (const float*)d_in[16];
    const float* fc_w     = (const float*)d_in[17];
    const float* fc_b     = (const float*)d_in[18];
    const float* mproj_w  = (const float*)d_in[19];
    const float* mproj_b  = (const float*)d_in[20];
    const float* down_w   = (const float*)d_in[21];
    const float* down_b   = (const float*)d_in[22];
    const float* up_w     = (const float*)d_in[23];
    const float* up_b     = (const float*)d_in[24];
    float* out = (float*)d_out;

    float* base = nullptr;
    cudaGetSymbolAddress((void**)&base, g_scratch);
    float* buf_ln    = base + OFF_LN;
    float* buf_qkv   = base + OFF_QKV;
    float* buf_attn  = base + OFF_ATTN;
    float* buf_x1    = base + OFF_X1;
    float* buf_x2    = base + OFF_X2;
    float* buf_qdec  = base + OFF_QDEC;
    float* buf_enckv = base + OFF_ENCKV;
    float* buf_h1    = base + OFF_H1;
    float* buf_h     = base + OFF_H;
    float* buf_a1    = base + OFF_A1;

    const int B = 4, T = 1024, Te = 257, C = 1024, H = 16;
    const int M  = B * T;   // 4096
    const int Me = B * Te;  // 1028
    const float scale = 0.125f;  // 1/sqrt(64)

    const int ATTN_SMEM = 4 * 64 * AT_PAD * sizeof(float);  // ~69.6 KB
    cudaFuncSetAttribute(attn_kernel<true>,  cudaFuncAttributeMaxDynamicSharedMemorySize, ATTN_SMEM);
    cudaFuncSetAttribute(attn_kernel<false>, cudaFuncAttributeMaxDynamicSharedMemorySize, ATTN_SMEM);

    // 1. ln1 = LN(x)
    ln_kernel<<<M, 256>>>(x, ln1_g, ln1_b, buf_ln);
    // 2. qkv = ln1 @ attn_w + attn_b        [4096, 3072]
    sgemm_kernel<<<dim3(3072 / 64, M / 64), 256>>>(buf_ln, C, attn_w, 3072, attn_b,
                                                   nullptr, nullptr, buf_qkv, 3072,
                                                   M, 3072, C, 0);
    // 3. self-attention (causal)            -> buf_attn [4096, 1024]
    attn_kernel<true><<<dim3(T / 64, H, B), 256, ATTN_SMEM>>>(
        buf_qkv,        (long)3072, (long)T * 3072,
        buf_qkv + 1024, (long)3072, (long)T * 3072,
        buf_qkv + 2048,
        buf_attn, T, T, scale);
    // 4. x1 = x + attn @ aproj_w + aproj_b
    sgemm_kernel<<<dim3(C / 64, M / 64), 256>>>(buf_attn, C, aproj_w, C, aproj_b,
                                                x, nullptr, buf_x1, C, M, C, C, 0);
    // 5. ln2 = LN(x1)
    ln_kernel<<<M, 256>>>(buf_x1, ln2_g, ln2_b, buf_ln);
    // 6. q_dec = ln2 @ ca_w[:, :1024] + ca_b[:1024]
    sgemm_kernel<<<dim3(C / 64, M / 64), 256>>>(buf_ln, C, ca_w, 3072, ca_b,
                                                nullptr, nullptr, buf_qdec, C, M, C, C, 0);
    // 7. enc_kv = enc @ ca_w[:, 1024:] + ca_b[1024:]   [1028, 2048]
    sgemm_kernel<<<dim3(2048 / 64, (Me + 63) / 64), 256>>>(enc, C, ca_w + 1024, 3072,
                                                           ca_b + 1024, nullptr, nullptr,
                                                           buf_enckv, 2048, Me, 2048, C, 0);
    // 8. cross-attention (non-causal, Tk=257) -> buf_attn (reused)
    attn_kernel<false><<<dim3(T / 64, H, B), 256, ATTN_SMEM>>>(
        buf_qdec,         (long)1024, (long)T * 1024,
        buf_enckv,        (long)2048, (long)Te * 2048,
        buf_enckv + 1024,
        buf_attn, T, Te, scale);
    // 9. x2 = x1 + ca_out @ caproj_w + caproj_b
    sgemm_kernel<<<dim3(C / 64, M / 64), 256>>>(buf_attn, C, caproj_w, C, caproj_b,
                                                buf_x1, nullptr, buf_x2, C, M, C, C, 0);
    // 10. ln3 = LN(x2)
    ln_kernel<<<M, 256>>>(buf_x2, ln3_g, ln3_b, buf_ln);
    // 11. h1 = gelu(ln3 @ fc_w + fc_b)      [4096, 4096]
    sgemm_kernel<<<dim3(4096 / 64, M / 64), 256>>>(buf_ln, C, fc_w, 4096, fc_b,
                                                   nullptr, nullptr, buf_h1, 4096,
                                                   M, 4096, C, 1);
    // 12. h = h1 @ mproj_w + mproj_b        [4096, 1024]
    sgemm_kernel<<<dim3(C / 64, M / 64), 256>>>(buf_h1, 4096, mproj_w, C, mproj_b,
                                                nullptr, nullptr, buf_h, C, M, C, 4096, 0);
    // 13. a1 = gelu(h @ down_w + down_b)    [4096, 256]
    sgemm_kernel<<<dim3(256 / 64, M / 64), 256>>>(buf_h, C, down_w, 256, down_b,
                                                  nullptr, nullptr, buf_a1, 256,
                                                  M, 256, C, 1);
    // 14. out = x2 + h + a1 @ up_w + up_b
    sgemm_kernel<<<dim3(C / 64, M / 64), 256>>>(buf_a1, 256, up_w, C, up_b,
                                                buf_h, buf_x2, out, C, M, C, 256, 0);
}

// round 2
// speedup vs baseline: 1.5150x; 1.5150x over previous
#include <cuda_runtime.h>
#include <math.h>
#include <stdint.h>

// ============================================================================
// Scratch (single __device__ array, no allocations anywhere)
// ============================================================================
__device__ float g_scratch[57679872];

#define OFF_LN     0ul
#define OFF_QKV    4194304ul
#define OFF_ATTN   16777216ul
#define OFF_X1     20971520ul
#define OFF_X2     25165824ul
#define OFF_QDEC   29360128ul
#define OFF_ENCKV  33554432ul
#define OFF_H1     35659776ul
#define OFF_H      52436992ul
#define OFF_A1     56631296ul

// ============================================================================
// LayerNorm: one block per row, C=1024, 256 threads
// ============================================================================
__global__ void ln_kernel(const float* __restrict__ x, const float* __restrict__ g,
                          const float* __restrict__ b, float* __restrict__ out) {
    const int C = 1024;
    int row = blockIdx.x;
    const float* xr = x + (size_t)row * C;
    float s = 0.f, ss = 0.f;
    for (int i = threadIdx.x; i < C; i += 256) { float v = xr[i]; s += v; ss += v * v; }
    #pragma unroll
    for (int o = 16; o; o >>= 1) {
        s  += __shfl_xor_sync(0xffffffffu, s, o);
        ss += __shfl_xor_sync(0xffffffffu, ss, o);
    }
    __shared__ float rs[8], rss[8];
    __shared__ float sh_m, sh_r;
    int w = threadIdx.x >> 5;
    if ((threadIdx.x & 31) == 0) { rs[w] = s; rss[w] = ss; }
    __syncthreads();
    if (threadIdx.x == 0) {
        float S = 0.f, SS = 0.f;
        #pragma unroll
        for (int i = 0; i < 8; i++) { S += rs[i]; SS += rss[i]; }
        float m = S / C;
        float v = SS / C - m * m;
        sh_m = m; sh_r = rsqrtf(v + 1e-5f);
    }
    __syncthreads();
    float m = sh_m, rst = sh_r;
    float* orow = out + (size_t)row * C;
    for (int i = threadIdx.x; i < C; i += 256)
        orow[i] = (xr[i] - m) * rst * g[i] + b[i];
}

// ============================================================================
// TF32 tensor-core GEMM: C[M,N] = A[M,K] @ B[K,N] + bias (+res1)(+res2), opt GELU
// BM=128, BN=128, BK=16, 256 threads (8 warps 4x2), warp tile 32x64,
// mma.m16n8k8 tf32, double-buffered smem with register staging.
// Requirements: N % 128 == 0, K % 16 == 0 (M arbitrary).
// ============================================================================
__device__ __forceinline__ float gelu_tanh(float v) {
    float u = 0.7978845608028654f * (v + 0.044715f * v * v * v);
    return 0.5f * v * (1.f + tanhf(u));
}

__device__ __forceinline__ float f2tf32(float f) {
    uint32_t u;
    asm("cvt.rna.tf32.f32 %0, %1;" : "=r"(u) : "f"(f));
    return __uint_as_float(u);
}

__device__ __forceinline__ void mma_tf32(float* c, const uint32_t* a, const uint32_t* b) {
    asm volatile(
        "mma.sync.aligned.m16n8k8.row.col.f32.tf32.tf32.f32 "
        "{%0,%1,%2,%3}, {%4,%5,%6,%7}, {%8,%9}, {%0,%1,%2,%3};"
        : "+f"(c[0]), "+f"(c[1]), "+f"(c[2]), "+f"(c[3])
        : "r"(a[0]), "r"(a[1]), "r"(a[2]), "r"(a[3]), "r"(b[0]), "r"(b[1]));
}

#define LDSA 20
#define LDSB 132

__global__ void tf32_gemm(const float* __restrict__ A, int lda,
                          const float* __restrict__ B, int ldb,
                          const float* __restrict__ bias,
                          const float* __restrict__ res1,
                          const float* __restrict__ res2,
                          float* __restrict__ C, int ldc,
                          int M, int N, int K, int dogelu) {
    __shared__ float As[2][128][LDSA];
    __shared__ float Bs[2][16][LDSB];

    int tid  = threadIdx.x;
    int lane = tid & 31;
    int warp = tid >> 5;
    int wm = warp & 3;       // 0..3  (rows, *32)
    int wn = warp >> 2;      // 0..1  (cols, *64)
    int g  = lane >> 2;      // group id 0..7
    int t4 = lane & 3;       // thread-in-group

    int bm = blockIdx.y * 128;
    int bn = blockIdx.x * 128;

    // --- global load indices ---
    int arow  = tid >> 2;           // 0..63 (+64 second pass)
    int acol  = (tid & 3) * 4;      // 0,4,8,12
    int bcol  = (tid & 31) * 4;     // 0..124
    int brow  = tid >> 5;           // 0..7 (+8 second pass)

    const float* Ap0 = A + (size_t)(bm + arow) * lda + acol;
    const float* Ap1 = A + (size_t)(bm + arow + 64) * lda + acol;
    bool av0 = (bm + arow) < M;
    bool av1 = (bm + arow + 64) < M;
    const float* Bp0 = B + (size_t)brow * ldb + bn + bcol;
    const float* Bp1 = B + (size_t)(brow + 8) * ldb + bn + bcol;

    float4 sa0, sa1, sb0, sb1;
    const float4 z4 = make_float4(0.f, 0.f, 0.f, 0.f);

    // prologue: load tile 0
    sa0 = av0 ? *(const float4*)(Ap0) : z4;
    sa1 = av1 ? *(const float4*)(Ap1) : z4;
    sb0 = *(const float4*)(Bp0);
    sb1 = *(const float4*)(Bp1);

    // store tile 0 (with tf32 rounding)
    {
        float* a0 = &As[0][arow][acol];
        a0[0] = f2tf32(sa0.x); a0[1] = f2tf32(sa0.y); a0[2] = f2tf32(sa0.z); a0[3] = f2tf32(sa0.w);
        float* a1 = &As[0][arow + 64][acol];
        a1[0] = f2tf32(sa1.x); a1[1] = f2tf32(sa1.y); a1[2] = f2tf32(sa1.z); a1[3] = f2tf32(sa1.w);
        float* b0 = &Bs[0][brow][bcol];
        b0[0] = f2tf32(sb0.x); b0[1] = f2tf32(sb0.y); b0[2] = f2tf32(sb0.z); b0[3] = f2tf32(sb0.w);
        float* b1 = &Bs[0][brow + 8][bcol];
        b1[0] = f2tf32(sb1.x); b1[1] = f2tf32(sb1.y); b1[2] = f2tf32(sb1.z); b1[3] = f2tf32(sb1.w);
    }
    __syncthreads();

    float acc[2][8][4];
    #pragma unroll
    for (int i = 0; i < 2; i++)
        #pragma unroll
        for (int j = 0; j < 8; j++)
            #pragma unroll
            for (int l = 0; l < 4; l++) acc[i][j][l] = 0.f;

    int nk = K >> 4;
    for (int t = 0; t < nk; t++) {
        int cur = t & 1;
        // prefetch next tile into registers
        if (t + 1 < nk) {
            int k0 = (t + 1) << 4;
            sa0 = av0 ? *(const float4*)(Ap0 + k0) : z4;
            sa1 = av1 ? *(const float4*)(Ap1 + k0) : z4;
            sb0 = *(const float4*)(Bp0 + (size_t)k0 * ldb);
            sb1 = *(const float4*)(Bp1 + (size_t)k0 * ldb);
        }

        // compute on current buffer
        #pragma unroll
        for (int ks = 0; ks < 16; ks += 8) {
            uint32_t af[2][4], bf[8][2];
            #pragma unroll
            for (int mt = 0; mt < 2; mt++) {
                int r0 = wm * 32 + mt * 16 + g;
                af[mt][0] = __float_as_uint(As[cur][r0][ks + t4]);
                af[mt][1] = __float_as_uint(As[cur][r0 + 8][ks + t4]);
                af[mt][2] = __float_as_uint(As[cur][r0][ks + t4 + 4]);
                af[mt][3] = __float_as_uint(As[cur][r0 + 8][ks + t4 + 4]);
            }
            #pragma unroll
            for (int nt = 0; nt < 8; nt++) {
                int c0 = wn * 64 + nt * 8 + g;
                bf[nt][0] = __float_as_uint(Bs[cur][ks + t4][c0]);
                bf[nt][1] = __float_as_uint(Bs[cur][ks + 4 + t4][c0]);
            }
            #pragma unroll
            for (int mt = 0; mt < 2; mt++)
                #pragma unroll
                for (int nt = 0; nt < 8; nt++)
                    mma_tf32(acc[mt][nt], af[mt], bf[nt]);
        }

        // store staged tile into the other buffer
        if (t + 1 < nk) {
            int nxt = (t + 1) & 1;
            float* a0 = &As[nxt][arow][acol];
            a0[0] = f2tf32(sa0.x); a0[1] = f2tf32(sa0.y); a0[2] = f2tf32(sa0.z); a0[3] = f2tf32(sa0.w);
            float* a1 = &As[nxt][arow + 64][acol];
            a1[0] = f2tf32(sa1.x); a1[1] = f2tf32(sa1.y); a1[2] = f2tf32(sa1.z); a1[3] = f2tf32(sa1.w);
            float* b0 = &Bs[nxt][brow][bcol];
            b0[0] = f2tf32(sb0.x); b0[1] = f2tf32(sb0.y); b0[2] = f2tf32(sb0.z); b0[3] = f2tf32(sb0.w);
            float* b1 = &Bs[nxt][brow + 8][bcol];
            b1[0] = f2tf32(sb1.x); b1[1] = f2tf32(sb1.y); b1[2] = f2tf32(sb1.z); b1[3] = f2tf32(sb1.w);
        }
        __syncthreads();
    }

    // epilogue
    #pragma unroll
    for (int mt = 0; mt < 2; mt++) {
        int row0 = bm + wm * 32 + mt * 16 + g;
        int row1 = row0 + 8;
        #pragma unroll
        for (int nt = 0; nt < 8; nt++) {
            int col = bn + wn * 64 + nt * 8 + 2 * t4;
            float bx = bias[col], by = bias[col + 1];
            float v00 = acc[mt][nt][0] + bx, v01 = acc[mt][nt][1] + by;
            float v10 = acc[mt][nt][2] + bx, v11 = acc[mt][nt][3] + by;
            if (row0 < M) {
                size_t i0 = (size_t)row0 * ldc + col;
                if (res1) { float2 r = *(const float2*)(res1 + i0); v00 += r.x; v01 += r.y; }
                if (res2) { float2 r = *(const float2*)(res2 + i0); v00 += r.x; v01 += r.y; }
                if (dogelu) { v00 = gelu_tanh(v00); v01 = gelu_tanh(v01); }
                *(float2*)(C + i0) = make_float2(v00, v01);
            }
            if (row1 < M) {
                size_t i1 = (size_t)row1 * ldc + col;
                if (res1) { float2 r = *(const float2*)(res1 + i1); v10 += r.x; v11 += r.y; }
                if (res2) { float2 r = *(const float2*)(res2 + i1); v10 += r.x; v11 += r.y; }
                if (dogelu) { v10 = gelu_tanh(v10); v11 = gelu_tanh(v11); }
                *(float2*)(C + i1) = make_float2(v10, v11);
            }
        }
    }
}

// ============================================================================
// Flash-style attention, fp32, D=64 per head, 64-row Q tiles, online softmax.
// ============================================================================
#define AT_PAD 68

template <bool CAUSAL>
__global__ void attn_kernel(const float* __restrict__ Qb, long qts, long qbs,
                            const float* __restrict__ Kb, long kts, long kbs,
                            const float* __restrict__ Vb,
                            float* __restrict__ O,
                            int Tq, int Tk, float scale) {
    extern __shared__ float sm[];
    float* Qs = sm;
    float* Ks = Qs + 64 * AT_PAD;
    float* Vs = Ks + 64 * AT_PAD;
    float* Ss = Vs + 64 * AT_PAD;

    int b = blockIdx.z, h = blockIdx.y, qt = blockIdx.x;
    int tid = threadIdx.x;
    const float* Qp = Qb + (size_t)b * qbs + (size_t)h * 64;
    const float* Kp = Kb + (size_t)b * kbs + (size_t)h * 64;
    const float* Vp = Vb + (size_t)b * kbs + (size_t)h * 64;

    #pragma unroll
    for (int it = 0; it < 4; it++) {
        int idx = tid + it * 256;
        int r = idx >> 4, c4 = (idx & 15) << 2;
        int t = qt * 64 + r;
        float4 v = *(const float4*)(Qp + (size_t)t * qts + c4);
        *(float4*)&Qs[r * AT_PAD + c4] = v;
    }

    int r  = tid >> 2;
    int c0 = (tid & 3) * 16;
    int q_global = qt * 64 + r;

    float o[16];
    #pragma unroll
    for (int j = 0; j < 16; j++) o[j] = 0.f;
    float mreg = -1e30f, lreg = 0.f;

    int ktiles = CAUSAL ? (qt + 1) : (Tk + 63) / 64;

    for (int kt = 0; kt < ktiles; kt++) {
        __syncthreads();
        #pragma unroll
        for (int it = 0; it < 4; it++) {
            int idx = tid + it * 256;
            int rr = idx >> 4, c4 = (idx & 15) << 2;
            int t = kt * 64 + rr;
            float4 kv, vv;
            if (t < Tk) {
                kv = *(const float4*)(Kp + (size_t)t * kts + c4);
                vv = *(const float4*)(Vp + (size_t)t * kts + c4);
            } else {
                kv = make_float4(0.f, 0.f, 0.f, 0.f);
                vv = kv;
            }
            *(float4*)&Ks[rr * AT_PAD + c4] = kv;
            *(float4*)&Vs[rr * AT_PAD + c4] = vv;
        }
        __syncthreads();

        float sv[16];
        #pragma unroll
        for (int j = 0; j < 16; j++) sv[j] = 0.f;
        #pragma unroll 4
        for (int d = 0; d < 64; d += 4) {
            float4 qv = *(const float4*)&Qs[r * AT_PAD + d];
            #pragma unroll
            for (int cc = 0; cc < 16; cc++) {
                float4 kv = *(const float4*)&Ks[(c0 + cc) * AT_PAD + d];
                sv[cc] += qv.x * kv.x + qv.y * kv.y + qv.z * kv.z + qv.w * kv.w;
            }
        }
        float tmax = -1e30f;
        #pragma unroll
        for (int cc = 0; cc < 16; cc++) {
            int kg = kt * 64 + c0 + cc;
            bool valid = (kg < Tk) && (!CAUSAL || kg <= q_global);
            sv[cc] = valid ? sv[cc] * scale : -1e30f;
            tmax = fmaxf(tmax, sv[cc]);
        }
        tmax = fmaxf(tmax, __shfl_xor_sync(0xffffffffu, tmax, 1));
        tmax = fmaxf(tmax, __shfl_xor_sync(0xffffffffu, tmax, 2));
        float mnew  = fmaxf(mreg, tmax);
        float alpha = __expf(mreg - mnew);
        float psum = 0.f;
        #pragma unroll
        for (int cc = 0; cc < 16; cc++) {
            float p = __expf(sv[cc] - mnew);
            Ss[r * AT_PAD + c0 + cc] = p;
            psum += p;
        }
        psum += __shfl_xor_sync(0xffffffffu, psum, 1);
        psum += __shfl_xor_sync(0xffffffffu, psum, 2);
        lreg = lreg * alpha + psum;
        mreg = mnew;
        #pragma unroll
        for (int j = 0; j < 16; j++) o[j] *= alpha;
        __syncwarp();

        #pragma unroll 4
        for (int k = 0; k < 64; k++) {
            float p = Ss[r * AT_PAD + k];
            #pragma unroll
            for (int j4 = 0; j4 < 4; j4++) {
                float4 vv = *(const float4*)&Vs[k * AT_PAD + c0 + j4 * 4];
                o[j4 * 4 + 0] += p * vv.x;
                o[j4 * 4 + 1] += p * vv.y;
                o[j4 * 4 + 2] += p * vv.z;
                o[j4 * 4 + 3] += p * vv.w;
            }
        }
    }

    float inv = 1.f / lreg;
    float* Op = O + ((size_t)(b * Tq + q_global)) * 1024 + h * 64 + c0;
    #pragma unroll
    for (int j4 = 0; j4 < 4; j4++) {
        float4 v = make_float4(o[j4 * 4 + 0] * inv, o[j4 * 4 + 1] * inv,
                               o[j4 * 4 + 2] * inv, o[j4 * 4 + 3] * inv);
        *(float4*)(Op + j4 * 4) = v;
    }
}

// ============================================================================
// Launch
// ============================================================================
extern "C" void kernel_launch(void* const* d_in, const int* in_sizes, int n_in,
                              void* d_out, int out_size) {
    (void)in_sizes; (void)n_in; (void)out_size;
    const float* x        = (const float*)d_in[0];
    const float* enc      = (const float*)d_in[1];
    const float* ln1_g    = (const float*)d_in[3];
    const float* ln1_b    = (const float*)d_in[4];
    const float* ln2_g    = (const float*)d_in[5];
    const float* ln2_b    = (const float*)d_in[6];
    const float* ln3_g    = (const float*)d_in[7];
    const float* ln3_b    = (const float*)d_in[8];
    const float* attn_w   = (const float*)d_in[9];
    const float* attn_b   = (const float*)d_in[10];
    const float* aproj_w  = (const float*)d_in[11];
    const float* aproj_b  = (const float*)d_in[12];
    const float* ca_w     = (const float*)d_in[13];
    const float* ca_b     = (const float*)d_in[14];
    const float* caproj_w = (const float*)d_in[15];
    const float* caproj_b = (const float*)d_in[16];
    const float* fc_w     = (const float*)d_in[17];
    const float* fc_b     = (const float*)d_in[18];
    const float* mproj_w  = (const float*)d_in[19];
    const float* mproj_b  = (const float*)d_in[20];
    const float* down_w   = (const float*)d_in[21];
    const float* down_b   = (const float*)d_in[22];
    const float* up_w     = (const float*)d_in[23];
    const float* up_b     = (const float*)d_in[24];
    float* out = (float*)d_out;

    float* base = nullptr;
    cudaGetSymbolAddress((void**)&base, g_scratch);
    float* buf_ln    = base + OFF_LN;
    float* buf_qkv   = base + OFF_QKV;
    float* buf_attn  = base + OFF_ATTN;
    float* buf_x1    = base + OFF_X1;
    float* buf_x2    = base + OFF_X2;
    float* buf_qdec  = base + OFF_QDEC;
    float* buf_enckv = base + OFF_ENCKV;
    float* buf_h1    = base + OFF_H1;
    float* buf_h     = base + OFF_H;
    float* buf_a1    = base + OFF_A1;

    const int B = 4, T = 1024, Te = 257, C = 1024, H = 16;
    const int M  = B * T;   // 4096
    const int Me = B * Te;  // 1028
    const float scale = 0.125f;

    const int ATTN_SMEM = 4 * 64 * AT_PAD * sizeof(float);
    cudaFuncSetAttribute(attn_kernel<true>,  cudaFuncAttributeMaxDynamicSharedMemorySize, ATTN_SMEM);
    cudaFuncSetAttribute(attn_kernel<false>, cudaFuncAttributeMaxDynamicSharedMemorySize, ATTN_SMEM);

    // 1. ln1 = LN(x)
    ln_kernel<<<M, 256>>>(x, ln1_g, ln1_b, buf_ln);
    // 2. qkv = ln1 @ attn_w + attn_b        [4096, 3072]
    tf32_gemm<<<dim3(3072 / 128, M / 128), 256>>>(buf_ln, C, attn_w, 3072, attn_b,
                                                  nullptr, nullptr, buf_qkv, 3072,
                                                  M, 3072, C, 0);
    // 3. self-attention (causal)
    attn_kernel<true><<<dim3(T / 64, H, B), 256, ATTN_SMEM>>>(
        buf_qkv,        (long)3072, (long)T * 3072,
        buf_qkv + 1024, (long)3072, (long)T * 3072,
        buf_qkv + 2048,
        buf_attn, T, T, scale);
    // 4. x1 = x + attn @ aproj_w + aproj_b
    tf32_gemm<<<dim3(C / 128, M / 128), 256>>>(buf_attn, C, aproj_w, C, aproj_b,
                                               x, nullptr, buf_x1, C, M, C, C, 0);
    // 5. ln2 = LN(x1)
    ln_kernel<<<M, 256>>>(buf_x1, ln2_g, ln2_b, buf_ln);
    // 6. q_dec = ln2 @ ca_w[:, :1024] + ca_b[:1024]
    tf32_gemm<<<dim3(C / 128, M / 128), 256>>>(buf_ln, C, ca_w, 3072, ca_b,
                                               nullptr, nullptr, buf_qdec, C, M, C, C, 0);
    // 7. enc_kv = enc @ ca_w[:, 1024:] + ca_b[1024:]   [1028, 2048]
    tf32_gemm<<<dim3(2048 / 128, (Me + 127) / 128), 256>>>(enc, C, ca_w + 1024, 3072,
                                                           ca_b + 1024, nullptr, nullptr,
                                                           buf_enckv, 2048, Me, 2048, C, 0);
    // 8. cross-attention (non-causal, Tk=257)
    attn_kernel<false><<<dim3(T / 64, H, B), 256, ATTN_SMEM>>>(
        buf_qdec,         (long)1024, (long)T * 1024,
        buf_enckv,        (long)2048, (long)Te * 2048,
        buf_enckv + 1024,
        buf_attn, T, Te, scale);
    // 9. x2 = x1 + ca_out @ caproj_w + caproj_b
    tf32_gemm<<<dim3(C / 128, M / 128), 256>>>(buf_attn, C, caproj_w, C, caproj_b,
                                               buf_x1, nullptr, buf_x2, C, M, C, C, 0);
    // 10. ln3 = LN(x2)
    ln_kernel<<<M, 256>>>(buf_x2, ln3_g, ln3_b, buf_ln);
    // 11. h1 = gelu(ln3 @ fc_w + fc_b)      [4096, 4096]
    tf32_gemm<<<dim3(4096 / 128, M / 128), 256>>>(buf_ln, C, fc_w, 4096, fc_b,
                                                  nullptr, nullptr, buf_h1, 4096,
                                                  M, 4096, C, 1);
    // 12. h = h1 @ mproj_w + mproj_b        [4096, 1024]
    tf32_gemm<<<dim3(C / 128, M / 128), 256>>>(buf_h1, 4096, mproj_w, C, mproj_b,
                                               nullptr, nullptr, buf_h, C, M, C, 4096, 0);
    // 13. a1 = gelu(h @ down_w + down_b)    [4096, 256]
    tf32_gemm<<<dim3(256 / 128, M / 128), 256>>>(buf_h, C, down_w, 256, down_b,
                                                 nullptr, nullptr, buf_a1, 256,
                                                 M, 256, C, 1);
    // 14. out = x2 + h + a1 @ up_w + up_b
    tf32_gemm<<<dim3(C / 128, M / 128), 256>>>(buf_a1, 256, up_w, C, up_b,
                                               buf_h, buf_x2, out, C, M, C, 256, 0);
}

// round 3
// speedup vs baseline: 5.6538x; 3.7318x over previous
#include <cuda_runtime.h>
#include <math.h>
#include <stdint.h>

// ============================================================================
// Scratch (single __device__ array, no allocations anywhere). ~304 MB.
// ============================================================================
__device__ float g_scratch[76034048];

#define OFF_LN        0ul
#define OFF_QKV       4194304ul
#define OFF_ATTN      16777216ul
#define OFF_X1        20971520ul
#define OFF_X2        25165824ul
#define OFF_QDEC      29360128ul
#define OFF_ENCKV     33554432ul
#define OFF_H1        35659776ul
#define OFF_H         52436992ul
#define OFF_A1        56631296ul
#define OFF_WT_ATTN   57679872ul
#define OFF_WT_APROJ  60825600ul
#define OFF_WT_CA     61874176ul
#define OFF_WT_CAPROJ 65019904ul
#define OFF_WT_FC     66068480ul
#define OFF_WT_MPROJ  70262784ul
#define OFF_WT_DOWN   74457088ul
#define OFF_WT_UP     74719232ul
#define OFF_ENCR      74981376ul

// ============================================================================
// Helpers
// ============================================================================
__device__ __forceinline__ float f2tf32(float f) {
    uint32_t u;
    asm("cvt.rna.tf32.f32 %0, %1;" : "=r"(u) : "f"(f));
    return __uint_as_float(u);
}

__device__ __forceinline__ float gelu_tanh(float v) {
    float u = 0.7978845608028654f * (v + 0.044715f * v * v * v);
    return 0.5f * v * (1.f + tanhf(u));
}

__device__ __forceinline__ uint32_t cvta_s(const void* p) {
    return (uint32_t)__cvta_generic_to_shared(p);
}

__device__ __forceinline__ void mma_tf32(float* c, const uint32_t* a, const uint32_t* b) {
    asm volatile(
        "mma.sync.aligned.m16n8k8.row.col.f32.tf32.tf32.f32 "
        "{%0,%1,%2,%3}, {%4,%5,%6,%7}, {%8,%9}, {%0,%1,%2,%3};"
        : "+f"(c[0]), "+f"(c[1]), "+f"(c[2]), "+f"(c[3])
        : "r"(a[0]), "r"(a[1]), "r"(a[2]), "r"(a[3]), "r"(b[0]), "r"(b[1]));
}

__device__ __forceinline__ void ldsm_x4(uint32_t* r, uint32_t addr) {
    asm volatile("ldmatrix.sync.aligned.m8n8.x4.shared.b16 {%0,%1,%2,%3}, [%4];"
        : "=r"(r[0]), "=r"(r[1]), "=r"(r[2]), "=r"(r[3]) : "r"(addr));
}

__device__ __forceinline__ void cp_async16(uint32_t dst, const void* src, unsigned sz) {
    asm volatile("cp.async.cg.shared.global [%0], [%1], 16, %2;"
        :: "r"(dst), "l"(src), "r"(sz));
}
__device__ __forceinline__ void cp_commit() { asm volatile("cp.async.commit_group;"); }
template <int N>
__device__ __forceinline__ void cp_wait() { asm volatile("cp.async.wait_group %0;" :: "n"(N)); }

// ============================================================================
// LayerNorm: one block per row, C=1024, 256 threads. Output RNA-rounded to tf32
// (all LN outputs feed tensor-core GEMM A operands).
// ============================================================================
__global__ void ln_kernel(const float* __restrict__ x, const float* __restrict__ g,
                          const float* __restrict__ b, float* __restrict__ out) {
    const int C = 1024;
    int row = blockIdx.x;
    const float* xr = x + (size_t)row * C;
    float s = 0.f, ss = 0.f;
    for (int i = threadIdx.x; i < C; i += 256) { float v = xr[i]; s += v; ss += v * v; }
    #pragma unroll
    for (int o = 16; o; o >>= 1) {
        s  += __shfl_xor_sync(0xffffffffu, s, o);
        ss += __shfl_xor_sync(0xffffffffu, ss, o);
    }
    __shared__ float rs[8], rss[8];
    __shared__ float sh_m, sh_r;
    int w = threadIdx.x >> 5;
    if ((threadIdx.x & 31) == 0) { rs[w] = s; rss[w] = ss; }
    __syncthreads();
    if (threadIdx.x == 0) {
        float S = 0.f, SS = 0.f;
        #pragma unroll
        for (int i = 0; i < 8; i++) { S += rs[i]; SS += rss[i]; }
        float m = S / C;
        float v = SS / C - m * m;
        sh_m = m; sh_r = rsqrtf(v + 1e-5f);
    }
    __syncthreads();
    float m = sh_m, rst = sh_r;
    float* orow = out + (size_t)row * C;
    for (int i = threadIdx.x; i < C; i += 256)
        orow[i] = f2tf32((xr[i] - m) * rst * g[i] + b[i]);
}

// ============================================================================
// Weight transpose + tf32 RNA round: Wt[n][k] = rna(W[k][n]). K,N mult of 32.
// ============================================================================
__global__ void transpose_rna(const float* __restrict__ W, float* __restrict__ Wt,
                              int K, int N) {
    __shared__ float t[32][33];
    int k0 = blockIdx.x * 32, n0 = blockIdx.y * 32;
    int tx = threadIdx.x & 31, ty = threadIdx.x >> 5;
    #pragma unroll
    for (int i = 0; i < 32; i += 8)
        t[ty + i][tx] = W[(size_t)(k0 + ty + i) * N + n0 + tx];
    __syncthreads();
    #pragma unroll
    for (int i = 0; i < 32; i += 8)
        Wt[(size_t)(n0 + ty + i) * K + k0 + tx] = f2tf32(t[tx][ty + i]);
}

__global__ void round_copy(const float* __restrict__ in, float* __restrict__ out, int n) {
    int i = blockIdx.x * 256 + threadIdx.x;
    if (i < n) out[i] = f2tf32(in[i]);
}

// ============================================================================
// NT TF32 GEMM: C[M,N] = A[M,K] @ Wt[N,K]^T + bias (+res1)(+res2), opt GELU,
// opt output RNA rounding. BM=BN=128, BK=16, 4-stage cp.async, ldmatrix frags.
// 256 threads, 8 warps (2 m x 4 n), warp tile 64x32. N%128==0, K%16==0.
// A and Wt must be pre-rounded tf32 values (stored as fp32 bits).
// ============================================================================
#define GST 4
#define GSD 20
#define GEMM_SMEM (2 * GST * 128 * GSD * 4)

__global__ void __launch_bounds__(256, 2) tf32_gemm(
    const float* __restrict__ A, int lda,
    const float* __restrict__ Bw, int ldb,
    const float* __restrict__ bias,
    const float* __restrict__ res1, const float* __restrict__ res2,
    float* __restrict__ C, int ldc,
    int M, int N, int K, int dogelu, int roundout) {
    extern __shared__ float gsm[];
    float* As = gsm;                       // [GST][128][GSD]  (m-major, k inner)
    float* Bs = gsm + GST * 128 * GSD;     // [GST][128][GSD]  (n-major, k inner)

    int tid = threadIdx.x, lane = tid & 31, warp = tid >> 5;
    int wm = warp & 1, wn = warp >> 1;
    int g = lane >> 2, t4 = lane & 3;
    int bm = blockIdx.y * 128, bn = blockIdx.x * 128;

    // cp.async mapping: each thread copies 2 A chunks + 2 B chunks per stage
    int crow = tid >> 2;
    int ckoff = (tid & 3) * 4;
    const float* Ag0 = A + (size_t)(bm + crow) * lda + ckoff;
    const float* Ag1 = A + (size_t)(bm + crow + 64) * lda + ckoff;
    const float* Bg0 = Bw + (size_t)(bn + crow) * ldb + ckoff;
    const float* Bg1 = Bw + (size_t)(bn + crow + 64) * ldb + ckoff;
    unsigned av0 = (bm + crow) < M ? 16u : 0u;
    unsigned av1 = (bm + crow + 64) < M ? 16u : 0u;

    const uint32_t stBytes = 128 * GSD * 4;
    uint32_t sa0 = cvta_s(&As[(size_t)crow * GSD + ckoff]);
    uint32_t sa1 = cvta_s(&As[(size_t)(crow + 64) * GSD + ckoff]);
    uint32_t sb0 = cvta_s(&Bs[(size_t)crow * GSD + ckoff]);
    uint32_t sb1 = cvta_s(&Bs[(size_t)(crow + 64) * GSD + ckoff]);

#define G_ISSUE(t_) do { \
        int slot_ = (t_) & 3; \
        size_t ko_ = (size_t)((t_) << 4); \
        cp_async16(sa0 + slot_ * stBytes, Ag0 + ko_, av0); \
        cp_async16(sa1 + slot_ * stBytes, Ag1 + ko_, av1); \
        cp_async16(sb0 + slot_ * stBytes, Bg0 + ko_, 16u); \
        cp_async16(sb1 + slot_ * stBytes, Bg1 + ko_, 16u); \
    } while (0)

    // ldmatrix lane offsets
    uint32_t a_ro = lane & 15, a_ko = (lane >> 4) << 2;
    uint32_t b_ro = (lane & 7) + ((lane >> 4) & 1) * 8, b_ko = ((lane >> 3) & 1) << 2;
    uint32_t abase = cvta_s(As) + ((wm * 64 + a_ro) * GSD + a_ko) * 4;
    uint32_t bbase = cvta_s(Bs) + ((wn * 32 + b_ro) * GSD + b_ko) * 4;

    float acc[4][4][4];
    #pragma unroll
    for (int i = 0; i < 4; i++)
        #pragma unroll
        for (int j = 0; j < 4; j++)
            #pragma unroll
            for (int l = 0; l < 4; l++) acc[i][j][l] = 0.f;

    int nk = K >> 4;
    #pragma unroll
    for (int s = 0; s < GST - 1; s++) { G_ISSUE(s); cp_commit(); }

    for (int t = 0; t < nk; t++) {
        cp_wait<GST - 2>();
        __syncthreads();
        if (t + GST - 1 < nk) G_ISSUE(t + GST - 1);
        cp_commit();

        int slot = t & 3;
        uint32_t aS = abase + slot * stBytes;
        uint32_t bS = bbase + slot * stBytes;
        #pragma unroll
        for (int ks = 0; ks < 16; ks += 8) {
            uint32_t af[4][4], bf[2][4];
            #pragma unroll
            for (int mt = 0; mt < 4; mt++)
                ldsm_x4(af[mt], aS + (mt * 16 * GSD + ks) * 4);
            #pragma unroll
            for (int np = 0; np < 2; np++)
                ldsm_x4(bf[np], bS + (np * 16 * GSD + ks) * 4);
            #pragma unroll
            for (int mt = 0; mt < 4; mt++)
                #pragma unroll
                for (int nt = 0; nt < 4; nt++)
                    mma_tf32(acc[mt][nt], af[mt], &bf[nt >> 1][(nt & 1) * 2]);
        }
    }
#undef G_ISSUE

    // epilogue
    #pragma unroll
    for (int mt = 0; mt < 4; mt++) {
        int row0 = bm + wm * 64 + mt * 16 + g;
        int row1 = row0 + 8;
        #pragma unroll
        for (int nt = 0; nt < 4; nt++) {
            int col = bn + wn * 32 + nt * 8 + 2 * t4;
            float bx = bias[col], by = bias[col + 1];
            float v00 = acc[mt][nt][0] + bx, v01 = acc[mt][nt][1] + by;
            float v10 = acc[mt][nt][2] + bx, v11 = acc[mt][nt][3] + by;
            if (row0 < M) {
                size_t i0 = (size_t)row0 * ldc + col;
                if (res1) { float2 r = *(const float2*)(res1 + i0); v00 += r.x; v01 += r.y; }
                if (res2) { float2 r = *(const float2*)(res2 + i0); v00 += r.x; v01 += r.y; }
                if (dogelu) { v00 = gelu_tanh(v00); v01 = gelu_tanh(v01); }
                if (roundout) { v00 = f2tf32(v00); v01 = f2tf32(v01); }
                *(float2*)(C + i0) = make_float2(v00, v01);
            }
            if (row1 < M) {
                size_t i1 = (size_t)row1 * ldc + col;
                if (res1) { float2 r = *(const float2*)(res1 + i1); v10 += r.x; v11 += r.y; }
                if (res2) { float2 r = *(const float2*)(res2 + i1); v10 += r.x; v11 += r.y; }
                if (dogelu) { v10 = gelu_tanh(v10); v11 = gelu_tanh(v11); }
                if (roundout) { v10 = f2tf32(v10); v11 = f2tf32(v11); }
                *(float2*)(C + i1) = make_float2(v10, v11);
            }
        }
    }
}

// ============================================================================
// Tensor-core flash attention, tf32 MMA, D=64. 64 Q rows/block, 4 warps.
// Q/K/V pre-rounded tf32. P rounded before l-sum (bias cancels in O = PV/l).
// Output RNA-rounded (feeds GEMM A operand). O merged-heads [B,Tq,1024].
// ============================================================================
#define ATS 68
#define ATTN_SMEM (4 * 64 * ATS * 4)

template <bool CAUSAL>
__global__ void __launch_bounds__(128) attn_mma(
    const float* __restrict__ Qb, long qts, long qbs,
    const float* __restrict__ Kb, long kts, long kbs,
    const float* __restrict__ Vb,
    float* __restrict__ O, int Tq, int Tk, float scale) {
    extern __shared__ float sm[];
    float* Qs = sm;              // [64][ATS]  q-major
    float* Ks = Qs + 64 * ATS;   // [64][ATS]  ktok-major (B operand for S)
    float* Vs = Ks + 64 * ATS;   // [64][ATS]  d-major / transposed (B operand for PV)
    float* Ps = Vs + 64 * ATS;   // [64][ATS]  q-major (A operand for PV)

    int b = blockIdx.z, h = blockIdx.y, qt = blockIdx.x;
    int tid = threadIdx.x, lane = tid & 31, wq = tid >> 5;
    int g = lane >> 2, t4 = lane & 3;

    const float* Qp = Qb + (size_t)b * qbs + h * 64;
    const float* Kp = Kb + (size_t)b * kbs + h * 64;
    const float* Vp = Vb + (size_t)b * kbs + h * 64;

    #pragma unroll
    for (int i = 0; i < 8; i++) {
        int idx = tid + i * 128;
        int r = idx >> 4, c4 = (idx & 15) << 2;
        float4 v = *(const float4*)(Qp + (size_t)(qt * 64 + r) * qts + c4);
        *(float4*)&Qs[r * ATS + c4] = v;
    }

    uint32_t a_ro = lane & 15, a_ko = (lane >> 4) << 2;
    uint32_t b_ro = (lane & 7) + ((lane >> 4) & 1) * 8, b_ko = ((lane >> 3) & 1) << 2;
    uint32_t qs_b = cvta_s(Qs) + ((wq * 16 + a_ro) * ATS + a_ko) * 4;
    uint32_t ks_b = cvta_s(Ks) + (b_ro * ATS + b_ko) * 4;
    uint32_t vs_b = cvta_s(Vs) + (b_ro * ATS + b_ko) * 4;
    uint32_t ps_b = cvta_s(Ps) + ((wq * 16 + a_ro) * ATS + a_ko) * 4;

    float m0 = -1e30f, m1 = -1e30f, l0 = 0.f, l1 = 0.f;
    float acc_o[8][4];
    #pragma unroll
    for (int i = 0; i < 8; i++)
        #pragma unroll
        for (int j = 0; j < 4; j++) acc_o[i][j] = 0.f;

    int q0 = qt * 64 + wq * 16 + g, q1 = q0 + 8;
    int nkt = CAUSAL ? (qt + 1) : (Tk + 63) >> 6;

    for (int kt = 0; kt < nkt; kt++) {
        __syncthreads();
        #pragma unroll
        for (int i = 0; i < 8; i++) {
            int idx = tid + i * 128;
            int rr = idx >> 4, c4 = (idx & 15) << 2;
            int t = kt * 64 + rr;
            float4 kv, vv;
            if (t < Tk) {
                kv = *(const float4*)(Kp + (size_t)t * kts + c4);
                vv = *(const float4*)(Vp + (size_t)t * kts + c4);
            } else {
                kv = make_float4(0.f, 0.f, 0.f, 0.f);
                vv = kv;
            }
            *(float4*)&Ks[rr * ATS + c4] = kv;
            Vs[(c4 + 0) * ATS + rr] = vv.x;
            Vs[(c4 + 1) * ATS + rr] = vv.y;
            Vs[(c4 + 2) * ATS + rr] = vv.z;
            Vs[(c4 + 3) * ATS + rr] = vv.w;
        }
        __syncthreads();

        // S = Q @ K^T
        float s[8][4];
        #pragma unroll
        for (int i = 0; i < 8; i++)
            #pragma unroll
            for (int j = 0; j < 4; j++) s[i][j] = 0.f;
        #pragma unroll
        for (int ks = 0; ks < 64; ks += 8) {
            uint32_t a[4];
            ldsm_x4(a, qs_b + ks * 4);
            #pragma unroll
            for (int np = 0; np < 4; np++) {
                uint32_t bf[4];
                ldsm_x4(bf, ks_b + (np * 16 * ATS + ks) * 4);
                mma_tf32(s[np * 2], a, bf);
                mma_tf32(s[np * 2 + 1], a, bf + 2);
            }
        }

        // scale + mask + row max
        float rm0 = -1e30f, rm1 = -1e30f;
        #pragma unroll
        for (int nt = 0; nt < 8; nt++) {
            int k0g = kt * 64 + nt * 8 + 2 * t4;
            int k1g = k0g + 1;
            bool c00 = (k0g < Tk) && (!CAUSAL || k0g <= q0);
            bool c01 = (k1g < Tk) && (!CAUSAL || k1g <= q0);
            bool c10 = (k0g < Tk) && (!CAUSAL || k0g <= q1);
            bool c11 = (k1g < Tk) && (!CAUSAL || k1g <= q1);
            s[nt][0] = c00 ? s[nt][0] * scale : -1e30f;
            s[nt][1] = c01 ? s[nt][1] * scale : -1e30f;
            s[nt][2] = c10 ? s[nt][2] * scale : -1e30f;
            s[nt][3] = c11 ? s[nt][3] * scale : -1e30f;
            rm0 = fmaxf(rm0, fmaxf(s[nt][0], s[nt][1]));
            rm1 = fmaxf(rm1, fmaxf(s[nt][2], s[nt][3]));
        }
        rm0 = fmaxf(rm0, __shfl_xor_sync(0xffffffffu, rm0, 1));
        rm0 = fmaxf(rm0, __shfl_xor_sync(0xffffffffu, rm0, 2));
        rm1 = fmaxf(rm1, __shfl_xor_sync(0xffffffffu, rm1, 1));
        rm1 = fmaxf(rm1, __shfl_xor_sync(0xffffffffu, rm1, 2));

        float mn0 = fmaxf(m0, rm0), mn1 = fmaxf(m1, rm1);
        float al0 = __expf(m0 - mn0), al1 = __expf(m1 - mn1);
        float ps0 = 0.f, ps1 = 0.f;
        int pr0 = (wq * 16 + g) * ATS, pr1 = (wq * 16 + g + 8) * ATS;
        #pragma unroll
        for (int nt = 0; nt < 8; nt++) {
            float p00 = f2tf32(__expf(s[nt][0] - mn0));
            float p01 = f2tf32(__expf(s[nt][1] - mn0));
            float p10 = f2tf32(__expf(s[nt][2] - mn1));
            float p11 = f2tf32(__expf(s[nt][3] - mn1));
            ps0 += p00 + p01;
            ps1 += p10 + p11;
            int c = nt * 8 + 2 * t4;
            *(float2*)&Ps[pr0 + c] = make_float2(p00, p01);
            *(float2*)&Ps[pr1 + c] = make_float2(p10, p11);
        }
        ps0 += __shfl_xor_sync(0xffffffffu, ps0, 1);
        ps0 += __shfl_xor_sync(0xffffffffu, ps0, 2);
        ps1 += __shfl_xor_sync(0xffffffffu, ps1, 1);
        ps1 += __shfl_xor_sync(0xffffffffu, ps1, 2);
        l0 = l0 * al0 + ps0;
        l1 = l1 * al1 + ps1;
        m0 = mn0; m1 = mn1;
        #pragma unroll
        for (int nt = 0; nt < 8; nt++) {
            acc_o[nt][0] *= al0; acc_o[nt][1] *= al0;
            acc_o[nt][2] *= al1; acc_o[nt][3] *= al1;
        }
        __syncwarp();

        // O += P @ V
        #pragma unroll
        for (int ks = 0; ks < 64; ks += 8) {
            uint32_t a[4];
            ldsm_x4(a, ps_b + ks * 4);
            #pragma unroll
            for (int np = 0; np < 4; np++) {
                uint32_t bf[4];
                ldsm_x4(bf, vs_b + (np * 16 * ATS + ks) * 4);
                mma_tf32(acc_o[np * 2], a, bf);
                mma_tf32(acc_o[np * 2 + 1], a, bf + 2);
            }
        }
    }

    float i0 = 1.f / l0, i1 = 1.f / l1;
    #pragma unroll
    for (int nt = 0; nt < 8; nt++) {
        int c = h * 64 + nt * 8 + 2 * t4;
        float* p0 = O + (size_t)(b * Tq + q0) * 1024 + c;
        float* p1 = O + (size_t)(b * Tq + q1) * 1024 + c;
        *(float2*)p0 = make_float2(f2tf32(acc_o[nt][0] * i0), f2tf32(acc_o[nt][1] * i0));
        *(float2*)p1 = make_float2(f2tf32(acc_o[nt][2] * i1), f2tf32(acc_o[nt][3] * i1));
    }
}

// ============================================================================
// Launch
// ============================================================================
extern "C" void kernel_launch(void* const* d_in, const int* in_sizes, int n_in,
                              void* d_out, int out_size) {
    (void)in_sizes; (void)n_in; (void)out_size;
    const float* x        = (const float*)d_in[0];
    const float* enc      = (const float*)d_in[1];
    const float* ln1_g    = (const float*)d_in[3];
    const float* ln1_b    = (const float*)d_in[4];
    const float* ln2_g    = (const float*)d_in[5];
    const float* ln2_b    = (const float*)d_in[6];
    const float* ln3_g    = (const float*)d_in[7];
    const float* ln3_b    = (const float*)d_in[8];
    const float* attn_w   = (const float*)d_in[9];
    const float* attn_b   = (const float*)d_in[10];
    const float* aproj_w  = (const float*)d_in[11];
    const float* aproj_b  = (const float*)d_in[12];
    const float* ca_w     = (const float*)d_in[13];
    const float* ca_b     = (const float*)d_in[14];
    const float* caproj_w = (const float*)d_in[15];
    const float* caproj_b = (const float*)d_in[16];
    const float* fc_w     = (const float*)d_in[17];
    const float* fc_b     = (const float*)d_in[18];
    const float* mproj_w  = (const float*)d_in[19];
    const float* mproj_b  = (const float*)d_in[20];
    const float* down_w   = (const float*)d_in[21];
    const float* down_b   = (const float*)d_in[22];
    const float* up_w     = (const float*)d_in[23];
    const float* up_b     = (const float*)d_in[24];
    float* out = (float*)d_out;

    float* base = nullptr;
    cudaGetSymbolAddress((void**)&base, g_scratch);
    float* buf_ln     = base + OFF_LN;
    float* buf_qkv    = base + OFF_QKV;
    float* buf_attn   = base + OFF_ATTN;
    float* buf_x1     = base + OFF_X1;
    float* buf_x2     = base + OFF_X2;
    float* buf_qdec   = base + OFF_QDEC;
    float* buf_enckv  = base + OFF_ENCKV;
    float* buf_h1     = base + OFF_H1;
    float* buf_h      = base + OFF_H;
    float* buf_a1     = base + OFF_A1;
    float* wt_attn    = base + OFF_WT_ATTN;
    float* wt_aproj   = base + OFF_WT_APROJ;
    float* wt_ca      = base + OFF_WT_CA;
    float* wt_caproj  = base + OFF_WT_CAPROJ;
    float* wt_fc      = base + OFF_WT_FC;
    float* wt_mproj   = base + OFF_WT_MPROJ;
    float* wt_down    = base + OFF_WT_DOWN;
    float* wt_up      = base + OFF_WT_UP;
    float* enc_r      = base + OFF_ENCR;

    const int B = 4, T = 1024, Te = 257, C = 1024, H = 16;
    const int M  = B * T;   // 4096
    const int Me = B * Te;  // 1028
    const float scale = 0.125f;

    cudaFuncSetAttribute(tf32_gemm, cudaFuncAttributeMaxDynamicSharedMemorySize, GEMM_SMEM);
    cudaFuncSetAttribute(attn_mma<true>,  cudaFuncAttributeMaxDynamicSharedMemorySize, ATTN_SMEM);
    cudaFuncSetAttribute(attn_mma<false>, cudaFuncAttributeMaxDynamicSharedMemorySize, ATTN_SMEM);

    // ---- one-time prep (runs per replay; ~70us of bandwidth) ----
    transpose_rna<<<dim3(C / 32, 3072 / 32), 256>>>(attn_w,   wt_attn,   C, 3072);
    transpose_rna<<<dim3(C / 32, 1024 / 32), 256>>>(aproj_w,  wt_aproj,  C, 1024);
    transpose_rna<<<dim3(C / 32, 3072 / 32), 256>>>(ca_w,     wt_ca,     C, 3072);
    transpose_rna<<<dim3(C / 32, 1024 / 32), 256>>>(caproj_w, wt_caproj, C, 1024);
    transpose_rna<<<dim3(C / 32, 4096 / 32), 256>>>(fc_w,     wt_fc,     C, 4096);
    transpose_rna<<<dim3(4096 / 32, 1024 / 32), 256>>>(mproj_w, wt_mproj, 4096, 1024);
    transpose_rna<<<dim3(C / 32, 256 / 32), 256>>>(down_w,   wt_down,   C, 256);
    transpose_rna<<<dim3(256 / 32, 1024 / 32), 256>>>(up_w,   wt_up,     256, 1024);
    round_copy<<<(Me * C + 255) / 256, 256>>>(enc, enc_r, Me * C);

    // 1. ln1 = LN(x)
    ln_kernel<<<M, 256>>>(x, ln1_g, ln1_b, buf_ln);
    // 2. qkv = ln1 @ attn_w + attn_b        [4096, 3072]  (rounded)
    tf32_gemm<<<dim3(3072 / 128, M / 128), 256, GEMM_SMEM>>>(
        buf_ln, C, wt_attn, C, attn_b, nullptr, nullptr, buf_qkv, 3072, M, 3072, C, 0, 1);
    // 3. self-attention (causal)
    attn_mma<true><<<dim3(T / 64, H, B), 128, ATTN_SMEM>>>(
        buf_qkv,        (long)3072, (long)T * 3072,
        buf_qkv + 1024, (long)3072, (long)T * 3072,
        buf_qkv + 2048, buf_attn, T, T, scale);
    // 4. x1 = x + attn @ aproj_w + aproj_b
    tf32_gemm<<<dim3(C / 128, M / 128), 256, GEMM_SMEM>>>(
        buf_attn, C, wt_aproj, C, aproj_b, x, nullptr, buf_x1, C, M, C, C, 0, 0);
    // 5. ln2 = LN(x1)
    ln_kernel<<<M, 256>>>(buf_x1, ln2_g, ln2_b, buf_ln);
    // 6. q_dec = ln2 @ ca_w[:, :1024] + ca_b[:1024]  (rounded)
    tf32_gemm<<<dim3(C / 128, M / 128), 256, GEMM_SMEM>>>(
        buf_ln, C, wt_ca, C, ca_b, nullptr, nullptr, buf_qdec, C, M, C, C, 0, 1);
    // 7. enc_kv = enc @ ca_w[:, 1024:] + ca_b[1024:]   [1028, 2048]  (rounded)
    tf32_gemm<<<dim3(2048 / 128, (Me + 127) / 128), 256, GEMM_SMEM>>>(
        enc_r, C, wt_ca + (size_t)1024 * C, C, ca_b + 1024, nullptr, nullptr,
        buf_enckv, 2048, Me, 2048, C, 0, 1);
    // 8. cross-attention (non-causal, Tk=257)
    attn_mma<false><<<dim3(T / 64, H, B), 128, ATTN_SMEM>>>(
        buf_qdec,  (long)1024, (long)T * 1024,
        buf_enckv, (long)2048, (long)Te * 2048,
        buf_enckv + 1024, buf_attn, T, Te, scale);
    // 9. x2 = x1 + ca_out @ caproj_w + caproj_b
    tf32_gemm<<<dim3(C / 128, M / 128), 256, GEMM_SMEM>>>(
        buf_attn, C, wt_caproj, C, caproj_b, buf_x1, nullptr, buf_x2, C, M, C, C, 0, 0);
    // 10. ln3 = LN(x2)
    ln_kernel<<<M, 256>>>(buf_x2, ln3_g, ln3_b, buf_ln);
    // 11. h1 = gelu(ln3 @ fc_w + fc_b)      [4096, 4096]  (rounded)
    tf32_gemm<<<dim3(4096 / 128, M / 128), 256, GEMM_SMEM>>>(
        buf_ln, C, wt_fc, C, fc_b, nullptr, nullptr, buf_h1, 4096, M, 4096, C, 1, 1);
    // 12. h = h1 @ mproj_w + mproj_b        [4096, 1024]  (rounded; also residual)
    tf32_gemm<<<dim3(C / 128, M / 128), 256, GEMM_SMEM>>>(
        buf_h1, 4096, wt_mproj, 4096, mproj_b, nullptr, nullptr, buf_h, C, M, C, 4096, 0, 1);
    // 13. a1 = gelu(h @ down_w + down_b)    [4096, 256]  (rounded)
    tf32_gemm<<<dim3(256 / 128, M / 128), 256, GEMM_SMEM>>>(
        buf_h, C, wt_down, C, down_b, nullptr, nullptr, buf_a1, 256, M, 256, C, 1, 1);
    // 14. out = x2 + h + a1 @ up_w + up_b
    tf32_gemm<<<dim3(C / 128, M / 128), 256, GEMM_SMEM>>>(
        buf_a1, 256, wt_up, 256, up_b, buf_h, buf_x2, out, C, M, C, 256, 0, 0);
}

// round 5
// speedup vs baseline: 8.3935x; 1.4846x over previous
#include <cuda_runtime.h>
#include <cuda_fp16.h>
#include <math.h>
#include <stdint.h>

// ============================================================================
// Scratch (single __device__ array, no allocations anywhere). ~230 MB.
// Offsets are in float units; half buffers occupy size/2 floats.
// ============================================================================
__device__ float g_scratch[57679872];

#define OFF_LN16       0ul
#define OFF_QKV16      2097152ul
#define OFF_ATTN16     8388608ul
#define OFF_X1         10485760ul
#define OFF_X2         14680064ul
#define OFF_QDEC16     18874368ul
#define OFF_ENCKV16    20971520ul
#define OFF_H1_16      22024192ul
#define OFF_H          30412800ul
#define OFF_H16        34607104ul
#define OFF_A1_16      36704256ul
#define OFF_WT_ATTN    37228544ul
#define OFF_WT_APROJ   38801408ul
#define OFF_WT_CA      39325696ul
#define OFF_WT_CAPROJ  40898560ul
#define OFF_WT_FC      41422848ul
#define OFF_WT_MPROJ   43520000ul
#define OFF_WT_DOWN    45617152ul
#define OFF_WT_UP      45748224ul
#define OFF_ENC16      45879296ul

// ============================================================================
// Helpers
// ============================================================================
__device__ __forceinline__ float gelu_tanh(float v) {
    float u = 0.7978845608028654f * (v + 0.044715f * v * v * v);
    return 0.5f * v * (1.f + tanhf(u));
}

__device__ __forceinline__ uint32_t cvta_s(const void* p) {
    return (uint32_t)__cvta_generic_to_shared(p);
}

__device__ __forceinline__ void mma_f16(float* c, const uint32_t* a, const uint32_t* b) {
    asm volatile(
        "mma.sync.aligned.m16n8k16.row.col.f32.f16.f16.f32 "
        "{%0,%1,%2,%3}, {%4,%5,%6,%7}, {%8,%9}, {%0,%1,%2,%3};"
        : "+f"(c[0]), "+f"(c[1]), "+f"(c[2]), "+f"(c[3])
        : "r"(a[0]), "r"(a[1]), "r"(a[2]), "r"(a[3]), "r"(b[0]), "r"(b[1]));
}

__device__ __forceinline__ void ldsm_x4(uint32_t* r, uint32_t addr) {
    asm volatile("ldmatrix.sync.aligned.m8n8.x4.shared.b16 {%0,%1,%2,%3}, [%4];"
        : "=r"(r[0]), "=r"(r[1]), "=r"(r[2]), "=r"(r[3]) : "r"(addr));
}

__device__ __forceinline__ void cp_async16(uint32_t dst, const void* src, unsigned sz) {
    asm volatile("cp.async.cg.shared.global [%0], [%1], 16, %2;"
        :: "r"(dst), "l"(src), "r"(sz));
}
__device__ __forceinline__ void cp_commit() { asm volatile("cp.async.commit_group;"); }
template <int N>
__device__ __forceinline__ void cp_wait() { asm volatile("cp.async.wait_group %0;" :: "n"(N)); }

// ============================================================================
// LayerNorm: one block per row, C=1024, 256 threads. fp16 (RN) output.
// ============================================================================
__global__ void ln_kernel(const float* __restrict__ x, const float* __restrict__ g,
                          const float* __restrict__ b, __half* __restrict__ out) {
    const int C = 1024;
    int row = blockIdx.x;
    const float* xr = x + (size_t)row * C;
    float s = 0.f, ss = 0.f;
    for (int i = threadIdx.x; i < C; i += 256) { float v = xr[i]; s += v; ss += v * v; }
    #pragma unroll
    for (int o = 16; o; o >>= 1) {
        s  += __shfl_xor_sync(0xffffffffu, s, o);
        ss += __shfl_xor_sync(0xffffffffu, ss, o);
    }
    __shared__ float rs[8], rss[8];
    __shared__ float sh_m, sh_r;
    int w = threadIdx.x >> 5;
    if ((threadIdx.x & 31) == 0) { rs[w] = s; rss[w] = ss; }
    __syncthreads();
    if (threadIdx.x == 0) {
        float S = 0.f, SS = 0.f;
        #pragma unroll
        for (int i = 0; i < 8; i++) { S += rs[i]; SS += rss[i]; }
        float m = S / C;
        float v = SS / C - m * m;
        sh_m = m; sh_r = rsqrtf(v + 1e-5f);
    }
    __syncthreads();
    float m = sh_m, rst = sh_r;
    __half* orow = out + (size_t)row * C;
    for (int i = threadIdx.x; i < C; i += 256)
        orow[i] = __float2half_rn((xr[i] - m) * rst * g[i] + b[i]);
}

// ============================================================================
// Weight transpose to fp16: Wt[n][k] = h(W[k][n]). K,N mult of 32.
// ============================================================================
__global__ void transpose_h(const float* __restrict__ W, __half* __restrict__ Wt,
                            int K, int N) {
    __shared__ float t[32][33];
    int k0 = blockIdx.x * 32, n0 = blockIdx.y * 32;
    int tx = threadIdx.x & 31, ty = threadIdx.x >> 5;
    #pragma unroll
    for (int i = 0; i < 32; i += 8)
        t[ty + i][tx] = W[(size_t)(k0 + ty + i) * N + n0 + tx];
    __syncthreads();
    #pragma unroll
    for (int i = 0; i < 32; i += 8)
        Wt[(size_t)(n0 + ty + i) * K + k0 + tx] = __float2half_rn(t[tx][ty + i]);
}

__global__ void round_copy_h(const float* __restrict__ in, __half* __restrict__ out, int n) {
    int i = blockIdx.x * 256 + threadIdx.x;
    if (i < n) out[i] = __float2half_rn(in[i]);
}

// ============================================================================
// FP16 NT GEMM: C[M,N] = A[M,K] @ Wt[N,K]^T + bias (+res1)(+res2), opt GELU.
// Outputs: Cf (fp32) and/or Ch (fp16), either may be null.
// BM=128, BN=128, BK=32 halves, 4-stage cp.async, ldmatrix b16, m16n8k16.
// 256 threads, 8 warps (2m x 4n), warp tile 64x32. N%128==0, K%32==0.
// ============================================================================
#define HKD 40                             // padded row: 32 data + 8 pad halves
#define HSTG 4
#define HSTAGE_HALFS (128 * HKD)           // per-operand per-stage halves
#define GEMM_SMEM (2 * HSTG * HSTAGE_HALFS * 2)

__global__ void __launch_bounds__(256, 2) h16_gemm(
    const __half* __restrict__ A, int lda,
    const __half* __restrict__ Bw, int ldb,
    const float* __restrict__ bias,
    const float* __restrict__ res1, const float* __restrict__ res2,
    float* __restrict__ Cf, __half* __restrict__ Ch, int ldc,
    int M, int K, int dogelu) {
    extern __shared__ __half hsm[];
    __half* As = hsm;                          // [HSTG][128][HKD]
    __half* Bs = hsm + HSTG * HSTAGE_HALFS;    // [HSTG][128][HKD]

    int tid = threadIdx.x, lane = tid & 31, warp = tid >> 5;
    int wm = warp & 1, wn = warp >> 1;
    int g = lane >> 2, t4 = lane & 3;
    int bm = blockIdx.y * 128, bn = blockIdx.x * 128;

    // cp.async mapping: row = tid>>1 (0..127), 2 chunks of 16B (8 halves) each
    int crow = tid >> 1;
    int cch = (tid & 1) * 2;                  // chunk index 0/2 -> halves 0/16
    const __half* Agp = A + (size_t)(bm + crow) * lda + cch * 8;
    const __half* Bgp = Bw + (size_t)(bn + crow) * ldb + cch * 8;
    unsigned aok = (bm + crow) < M ? 16u : 0u;
    uint32_t sa = cvta_s(As) + (crow * HKD + cch * 8) * 2;
    uint32_t sb = cvta_s(Bs) + (crow * HKD + cch * 8) * 2;
    const uint32_t stB = HSTAGE_HALFS * 2;

#define H_ISSUE(t_) do { \
        int slot_ = (t_) & (HSTG - 1); \
        size_t ko_ = (size_t)((t_) << 5); \
        cp_async16(sa + slot_ * stB,       Agp + ko_,      aok); \
        cp_async16(sa + slot_ * stB + 16,  Agp + ko_ + 8,  aok); \
        cp_async16(sb + slot_ * stB,       Bgp + ko_,      16u); \
        cp_async16(sb + slot_ * stB + 16,  Bgp + ko_ + 8,  16u); \
    } while (0)

    // ldmatrix lane offsets (halves)
    uint32_t a_ro = lane & 15, a_ko = (lane >> 4) * 8;
    uint32_t b_ro = (lane & 7) + ((lane >> 4) & 1) * 8, b_ko = ((lane >> 3) & 1) * 8;
    uint32_t abase = cvta_s(As) + ((wm * 64 + a_ro) * HKD + a_ko) * 2;
    uint32_t bbase = cvta_s(Bs) + ((wn * 32 + b_ro) * HKD + b_ko) * 2;

    float acc[4][4][4];
    #pragma unroll
    for (int i = 0; i < 4; i++)
        #pragma unroll
        for (int j = 0; j < 4; j++)
            #pragma unroll
            for (int l = 0; l < 4; l++) acc[i][j][l] = 0.f;

    int nk = K >> 5;
    #pragma unroll
    for (int s = 0; s < HSTG - 1; s++) { H_ISSUE(s); cp_commit(); }

    for (int t = 0; t < nk; t++) {
        cp_wait<HSTG - 2>();
        __syncthreads();
        if (t + HSTG - 1 < nk) H_ISSUE(t + HSTG - 1);
        cp_commit();

        int slot = t & (HSTG - 1);
        uint32_t aS = abase + slot * stB;
        uint32_t bS = bbase + slot * stB;
        #pragma unroll
        for (int ks = 0; ks < 32; ks += 16) {
            uint32_t af[4][4], bf[2][4];
            #pragma unroll
            for (int mt = 0; mt < 4; mt++)
                ldsm_x4(af[mt], aS + (mt * 16 * HKD + ks) * 2);
            #pragma unroll
            for (int np = 0; np < 2; np++)
                ldsm_x4(bf[np], bS + (np * 16 * HKD + ks) * 2);
            #pragma unroll
            for (int mt = 0; mt < 4; mt++)
                #pragma unroll
                for (int nt = 0; nt < 4; nt++)
                    mma_f16(acc[mt][nt], af[mt], &bf[nt >> 1][(nt & 1) * 2]);
        }
    }
#undef H_ISSUE

    // epilogue
    #pragma unroll
    for (int mt = 0; mt < 4; mt++) {
        int row0 = bm + wm * 64 + mt * 16 + g;
        int row1 = row0 + 8;
        #pragma unroll
        for (int nt = 0; nt < 4; nt++) {
            int col = bn + wn * 32 + nt * 8 + 2 * t4;
            float bx = bias[col], by = bias[col + 1];
            float v00 = acc[mt][nt][0] + bx, v01 = acc[mt][nt][1] + by;
            float v10 = acc[mt][nt][2] + bx, v11 = acc[mt][nt][3] + by;
            if (row0 < M) {
                size_t i0 = (size_t)row0 * ldc + col;
                if (res1) { float2 r = *(const float2*)(res1 + i0); v00 += r.x; v01 += r.y; }
                if (res2) { float2 r = *(const float2*)(res2 + i0); v00 += r.x; v01 += r.y; }
                if (dogelu) { v00 = gelu_tanh(v00); v01 = gelu_tanh(v01); }
                if (Cf) *(float2*)(Cf + i0) = make_float2(v00, v01);
                if (Ch) *(half2*)(Ch + i0) =
                    make_half2(__float2half_rn(v00), __float2half_rn(v01));
            }
            if (row1 < M) {
                size_t i1 = (size_t)row1 * ldc + col;
                if (res1) { float2 r = *(const float2*)(res1 + i1); v10 += r.x; v11 += r.y; }
                if (res2) { float2 r = *(const float2*)(res2 + i1); v10 += r.x; v11 += r.y; }
                if (dogelu) { v10 = gelu_tanh(v10); v11 = gelu_tanh(v11); }
                if (Cf) *(float2*)(Cf + i1) = make_float2(v10, v11);
                if (Ch) *(half2*)(Ch + i1) =
                    make_half2(__float2half_rn(v10), __float2half_rn(v11));
            }
        }
    }
}

// ============================================================================
// FP16 tensor-core flash attention, D=64, 64 Q rows/block, 4 warps,
// m16n8k16 for S=QK^T and O=PV, fp32 softmax stats, fp16 output.
// ============================================================================
#define ATS 72   // padded row in halves (64 data + 8 pad); 144B rows, 16B aligned

template <bool CAUSAL>
__global__ void __launch_bounds__(128) attn_h16(
    const __half* __restrict__ Qb, long qts, long qbs,
    const __half* __restrict__ Kb, long kts, long kbs,
    const __half* __restrict__ Vb,
    __half* __restrict__ O, int Tq, int Tk, float scale) {
    __shared__ __half Qs[64 * ATS];
    __shared__ __half Ks[64 * ATS];
    __shared__ __half Vs[64 * ATS];   // transposed: [d][ktok]
    __shared__ __half Ps[64 * ATS];

    int b = blockIdx.z, h = blockIdx.y, qt = blockIdx.x;
    int tid = threadIdx.x, lane = tid & 31, wq = tid >> 5;
    int g = lane >> 2, t4 = lane & 3;

    const __half* Qp = Qb + (size_t)b * qbs + h * 64;
    const __half* Kp = Kb + (size_t)b * kbs + h * 64;
    const __half* Vp = Vb + (size_t)b * kbs + h * 64;

    // load Q tile: 64x64 halves, 16B chunks
    #pragma unroll
    for (int i = 0; i < 4; i++) {
        int idx = tid + i * 128;
        int r = idx >> 3, c8 = (idx & 7) * 8;
        uint4 v = *(const uint4*)(Qp + (size_t)(qt * 64 + r) * qts + c8);
        *(uint4*)&Qs[r * ATS + c8] = v;
    }

    uint32_t a_ro = lane & 15, a_ko = (lane >> 4) * 8;
    uint32_t b_ro = (lane & 7) + ((lane >> 4) & 1) * 8, b_ko = ((lane >> 3) & 1) * 8;
    uint32_t qs_b = cvta_s(Qs) + ((wq * 16 + a_ro) * ATS + a_ko) * 2;
    uint32_t ks_b = cvta_s(Ks) + (b_ro * ATS + b_ko) * 2;
    uint32_t vs_b = cvta_s(Vs) + (b_ro * ATS + b_ko) * 2;
    uint32_t ps_b = cvta_s(Ps) + ((wq * 16 + a_ro) * ATS + a_ko) * 2;

    float m0 = -1e30f, m1 = -1e30f, l0 = 0.f, l1 = 0.f;
    float acc_o[8][4];
    #pragma unroll
    for (int i = 0; i < 8; i++)
        #pragma unroll
        for (int j = 0; j < 4; j++) acc_o[i][j] = 0.f;

    int q0 = qt * 64 + wq * 16 + g, q1 = q0 + 8;
    int nkt = CAUSAL ? (qt + 1) : (Tk + 63) >> 6;

    for (int kt = 0; kt < nkt; kt++) {
        __syncthreads();
        #pragma unroll
        for (int i = 0; i < 4; i++) {
            int idx = tid + i * 128;
            int rr = idx >> 3, c8 = (idx & 7) * 8;
            int t = kt * 64 + rr;
            union { uint4 u; __half hh[8]; } kv, vv;
            if (t < Tk) {
                kv.u = *(const uint4*)(Kp + (size_t)t * kts + c8);
                vv.u = *(const uint4*)(Vp + (size_t)t * kts + c8);
            } else {
                kv.u = make_uint4(0, 0, 0, 0);
                vv.u = kv.u;
            }
            *(uint4*)&Ks[rr * ATS + c8] = kv.u;
            #pragma unroll
            for (int j = 0; j < 8; j++)
                Vs[(c8 + j) * ATS + rr] = vv.hh[j];
        }
        __syncthreads();

        // S = Q @ K^T  (fp32 accum)
        float s[8][4];
        #pragma unroll
        for (int i = 0; i < 8; i++)
            #pragma unroll
            for (int j = 0; j < 4; j++) s[i][j] = 0.f;
        #pragma unroll
        for (int ks = 0; ks < 64; ks += 16) {
            uint32_t a[4];
            ldsm_x4(a, qs_b + ks * 2);
            #pragma unroll
            for (int np = 0; np < 4; np++) {
                uint32_t bf[4];
                ldsm_x4(bf, ks_b + (np * 16 * ATS + ks) * 2);
                mma_f16(s[np * 2], a, bf);
                mma_f16(s[np * 2 + 1], a, bf + 2);
            }
        }

        // scale + mask + row max
        float rm0 = -1e30f, rm1 = -1e30f;
        #pragma unroll
        for (int nt = 0; nt < 8; nt++) {
            int k0g = kt * 64 + nt * 8 + 2 * t4;
            int k1g = k0g + 1;
            bool c00 = (k0g < Tk) && (!CAUSAL || k0g <= q0);
            bool c01 = (k1g < Tk) && (!CAUSAL || k1g <= q0);
            bool c10 = (k0g < Tk) && (!CAUSAL || k0g <= q1);
            bool c11 = (k1g < Tk) && (!CAUSAL || k1g <= q1);
            s[nt][0] = c00 ? s[nt][0] * scale : -1e30f;
            s[nt][1] = c01 ? s[nt][1] * scale : -1e30f;
            s[nt][2] = c10 ? s[nt][2] * scale : -1e30f;
            s[nt][3] = c11 ? s[nt][3] * scale : -1e30f;
            rm0 = fmaxf(rm0, fmaxf(s[nt][0], s[nt][1]));
            rm1 = fmaxf(rm1, fmaxf(s[nt][2], s[nt][3]));
        }
        rm0 = fmaxf(rm0, __shfl_xor_sync(0xffffffffu, rm0, 1));
        rm0 = fmaxf(rm0, __shfl_xor_sync(0xffffffffu, rm0, 2));
        rm1 = fmaxf(rm1, __shfl_xor_sync(0xffffffffu, rm1, 1));
        rm1 = fmaxf(rm1, __shfl_xor_sync(0xffffffffu, rm1, 2));

        float mn0 = fmaxf(m0, rm0), mn1 = fmaxf(m1, rm1);
        float al0 = __expf(m0 - mn0), al1 = __expf(m1 - mn1);
        float ps0 = 0.f, ps1 = 0.f;
        int pr0 = (wq * 16 + g) * ATS, pr1 = (wq * 16 + g + 8) * ATS;
        #pragma unroll
        for (int nt = 0; nt < 8; nt++) {
            __half p00 = __float2half_rn(__expf(s[nt][0] - mn0));
            __half p01 = __float2half_rn(__expf(s[nt][1] - mn0));
            __half p10 = __float2half_rn(__expf(s[nt][2] - mn1));
            __half p11 = __float2half_rn(__expf(s[nt][3] - mn1));
            ps0 += __half2float(p00) + __half2float(p01);
            ps1 += __half2float(p10) + __half2float(p11);
            int c = nt * 8 + 2 * t4;
            *(half2*)&Ps[pr0 + c] = make_half2(p00, p01);
            *(half2*)&Ps[pr1 + c] = make_half2(p10, p11);
        }
        ps0 += __shfl_xor_sync(0xffffffffu, ps0, 1);
        ps0 += __shfl_xor_sync(0xffffffffu, ps0, 2);
        ps1 += __shfl_xor_sync(0xffffffffu, ps1, 1);
        ps1 += __shfl_xor_sync(0xffffffffu, ps1, 2);
        l0 = l0 * al0 + ps0;
        l1 = l1 * al1 + ps1;
        m0 = mn0; m1 = mn1;
        #pragma unroll
        for (int nt = 0; nt < 8; nt++) {
            acc_o[nt][0] *= al0; acc_o[nt][1] *= al0;
            acc_o[nt][2] *= al1; acc_o[nt][3] *= al1;
        }
        __syncwarp();

        // O += P @ V   (A = Ps rows q, k=ktok; B = Vs rows d, k=ktok)
        #pragma unroll
        for (int ks = 0; ks < 64; ks += 16) {
            uint32_t a[4];
            ldsm_x4(a, ps_b + ks * 2);
            #pragma unroll
            for (int np = 0; np < 4; np++) {
                uint32_t bf[4];
                ldsm_x4(bf, vs_b + (np * 16 * ATS + ks) * 2);
                mma_f16(acc_o[np * 2], a, bf);
                mma_f16(acc_o[np * 2 + 1], a, bf + 2);
            }
        }
    }

    float i0 = 1.f / l0, i1 = 1.f / l1;
    #pragma unroll
    for (int nt = 0; nt < 8; nt++) {
        int c = h * 64 + nt * 8 + 2 * t4;
        __half* p0 = O + (size_t)(b * Tq + q0) * 1024 + c;
        __half* p1 = O + (size_t)(b * Tq + q1) * 1024 + c;
        *(half2*)p0 = make_half2(__float2half_rn(acc_o[nt][0] * i0),
                                 __float2half_rn(acc_o[nt][1] * i0));
        *(half2*)p1 = make_half2(__float2half_rn(acc_o[nt][2] * i1),
                                 __float2half_rn(acc_o[nt][3] * i1));
    }
}

// ============================================================================
// Launch
// ============================================================================
extern "C" void kernel_launch(void* const* d_in, const int* in_sizes, int n_in,
                              void* d_out, int out_size) {
    (void)in_sizes; (void)n_in; (void)out_size;
    const float* x        = (const float*)d_in[0];
    const float* enc      = (const float*)d_in[1];
    const float* ln1_g    = (const float*)d_in[3];
    const float* ln1_b    = (const float*)d_in[4];
    const float* ln2_g    = (const float*)d_in[5];
    const float* ln2_b    = (const float*)d_in[6];
    const float* ln3_g    = (const float*)d_in[7];
    const float* ln3_b    = (const float*)d_in[8];
    const float* attn_w   = (const float*)d_in[9];
    const float* attn_b   = (const float*)d_in[10];
    const float* aproj_w  = (const float*)d_in[11];
    const float* aproj_b  = (const float*)d_in[12];
    const float* ca_w     = (const float*)d_in[13];
    const float* ca_b     = (const float*)d_in[14];
    const float* caproj_w = (const float*)d_in[15];
    const float* caproj_b = (const float*)d_in[16];
    const float* fc_w     = (const float*)d_in[17];
    const float* fc_b     = (const float*)d_in[18];
    const float* mproj_w  = (const float*)d_in[19];
    const float* mproj_b  = (const float*)d_in[20];
    const float* down_w   = (const float*)d_in[21];
    const float* down_b   = (const float*)d_in[22];
    const float* up_w     = (const float*)d_in[23];
    const float* up_b     = (const float*)d_in[24];
    float* out = (float*)d_out;

    float* base = nullptr;
    cudaGetSymbolAddress((void**)&base, g_scratch);
    __half* ln16     = (__half*)(base + OFF_LN16);
    __half* qkv16    = (__half*)(base + OFF_QKV16);
    __half* attn16   = (__half*)(base + OFF_ATTN16);
    float*  x1       = base + OFF_X1;
    float*  x2       = base + OFF_X2;
    __half* qdec16   = (__half*)(base + OFF_QDEC16);
    __half* enckv16  = (__half*)(base + OFF_ENCKV16);
    __half* h1_16    = (__half*)(base + OFF_H1_16);
    float*  hbuf     = base + OFF_H;
    __half* h16      = (__half*)(base + OFF_H16);
    __half* a1_16    = (__half*)(base + OFF_A1_16);
    __half* wt_attn  = (__half*)(base + OFF_WT_ATTN);
    __half* wt_aproj = (__half*)(base + OFF_WT_APROJ);
    __half* wt_ca    = (__half*)(base + OFF_WT_CA);
    __half* wt_caproj= (__half*)(base + OFF_WT_CAPROJ);
    __half* wt_fc    = (__half*)(base + OFF_WT_FC);
    __half* wt_mproj = (__half*)(base + OFF_WT_MPROJ);
    __half* wt_down  = (__half*)(base + OFF_WT_DOWN);
    __half* wt_up    = (__half*)(base + OFF_WT_UP);
    __half* enc16    = (__half*)(base + OFF_ENC16);

    const int B = 4, T = 1024, Te = 257, C = 1024, H = 16;
    const int M  = B * T;   // 4096
    const int Me = B * Te;  // 1028
    const float scale = 0.125f;

    cudaFuncSetAttribute(h16_gemm, cudaFuncAttributeMaxDynamicSharedMemorySize, GEMM_SMEM);

    // ---- prep: transpose weights to fp16, round enc to fp16 ----
    transpose_h<<<dim3(C / 32, 3072 / 32), 256>>>(attn_w,   wt_attn,   C, 3072);
    transpose_h<<<dim3(C / 32, 1024 / 32), 256>>>(aproj_w,  wt_aproj,  C, 1024);
    transpose_h<<<dim3(C / 32, 3072 / 32), 256>>>(ca_w,     wt_ca,     C, 3072);
    transpose_h<<<dim3(C / 32, 1024 / 32), 256>>>(caproj_w, wt_caproj, C, 1024);
    transpose_h<<<dim3(C / 32, 4096 / 32), 256>>>(fc_w,     wt_fc,     C, 4096);
    transpose_h<<<dim3(4096 / 32, 1024 / 32), 256>>>(mproj_w, wt_mproj, 4096, 1024);
    transpose_h<<<dim3(C / 32, 256 / 32), 256>>>(down_w,   wt_down,   C, 256);
    transpose_h<<<dim3(256 / 32, 1024 / 32), 256>>>(up_w,   wt_up,     256, 1024);
    round_copy_h<<<(Me * C + 255) / 256, 256>>>(enc, enc16, Me * C);

    // 1. ln1 = LN(x) -> fp16
    ln_kernel<<<M, 256>>>(x, ln1_g, ln1_b, ln16);
    // 2. qkv = ln1 @ attn_w + attn_b   [4096, 3072] fp16
    h16_gemm<<<dim3(3072 / 128, M / 128), 256, GEMM_SMEM>>>(
        ln16, C, wt_attn, C, attn_b, nullptr, nullptr, nullptr, qkv16, 3072, M, C, 0);
    // 3. self-attention (causal) -> fp16
    attn_h16<true><<<dim3(T / 64, H, B), 128>>>(
        qkv16,        (long)3072, (long)T * 3072,
        qkv16 + 1024, (long)3072, (long)T * 3072,
        qkv16 + 2048, attn16, T, T, scale);
    // 4. x1 = x + attn @ aproj_w + aproj_b   (fp32)
    h16_gemm<<<dim3(1024 / 128, M / 128), 256, GEMM_SMEM>>>(
        attn16, C, wt_aproj, C, aproj_b, x, nullptr, x1, nullptr, C, M, C, 0);
    // 5. ln2 = LN(x1) -> fp16
    ln_kernel<<<M, 256>>>(x1, ln2_g, ln2_b, ln16);
    // 6. q_dec = ln2 @ ca_w[:, :1024] + ca_b[:1024]  fp16
    h16_gemm<<<dim3(1024 / 128, M / 128), 256, GEMM_SMEM>>>(
        ln16, C, wt_ca, C, ca_b, nullptr, nullptr, nullptr, qdec16, C, M, C, 0);
    // 7. enc_kv = enc @ ca_w[:, 1024:] + ca_b[1024:]  [1028, 2048] fp16
    h16_gemm<<<dim3(2048 / 128, (Me + 127) / 128), 256, GEMM_SMEM>>>(
        enc16, C, wt_ca + (size_t)1024 * C, C, ca_b + 1024, nullptr, nullptr,
        nullptr, enckv16, 2048, Me, C, 0);
    // 8. cross-attention (non-causal, Tk=257) -> fp16
    attn_h16<false><<<dim3(T / 64, H, B), 128>>>(
        qdec16,  (long)1024, (long)T * 1024,
        enckv16, (long)2048, (long)Te * 2048,
        enckv16 + 1024, attn16, T, Te, scale);
    // 9. x2 = x1 + ca_out @ caproj_w + caproj_b   (fp32)
    h16_gemm<<<dim3(1024 / 128, M / 128), 256, GEMM_SMEM>>>(
        attn16, C, wt_caproj, C, caproj_b, x1, nullptr, x2, nullptr, C, M, C, 0);
    // 10. ln3 = LN(x2) -> fp16
    ln_kernel<<<M, 256>>>(x2, ln3_g, ln3_b, ln16);
    // 11. h1 = gelu(ln3 @ fc_w + fc_b)   [4096, 4096] fp16
    h16_gemm<<<dim3(4096 / 128, M / 128), 256, GEMM_SMEM>>>(
        ln16, C, wt_fc, C, fc_b, nullptr, nullptr, nullptr, h1_16, 4096, M, C, 1);
    // 12. h = h1 @ mproj_w + mproj_b   [4096, 1024]  fp32 + fp16
    h16_gemm<<<dim3(1024 / 128, M / 128), 256, GEMM_SMEM>>>(
        h1_16, 4096, wt_mproj, 4096, mproj_b, nullptr, nullptr, hbuf, h16, C, M, 4096, 0);
    // 13. a1 = gelu(h @ down_w + down_b)   [4096, 256] fp16
    h16_gemm<<<dim3(256 / 128, M / 128), 256, GEMM_SMEM>>>(
        h16, C, wt_down, C, down_b, nullptr, nullptr, nullptr, a1_16, 256, M, C, 1);
    // 14. out = x2 + h + a1 @ up_w + up_b   (fp32)
    h16_gemm<<<dim3(1024 / 128, M / 128), 256, GEMM_SMEM>>>(
        a1_16, 256, wt_up, 256, up_b, hbuf, x2, out, nullptr, C, M, 256, 0);
}